// round 8
// baseline (speedup 1.0000x reference)
#include <cuda_runtime.h>
#include <cstdint>

#define N_NODES 50000
#define F_IN    1024
#define F_HID   256
#define F_OUT   256
#define EPS     1e-5f
#define E_MAX   1048576
#define NB_SCAN 196        // ceil(50000/256)

// ---------------- scratch (allocation-free: device globals) ----------------
__device__ __align__(256) float g_h[(size_t)N_NODES * F_HID];
__device__ __align__(256) float g_agg[(size_t)N_NODES * F_HID];
__device__ float g_deg[N_NODES];
__device__ float g_dinv[N_NODES];
__device__ int   g_cnt[N_NODES];
__device__ int   g_offs[N_NODES];
__device__ int   g_cursor[N_NODES];
__device__ int   g_chunk[256];
__device__ int   g_chunkbase[256];
__device__ int   g_csr_src[E_MAX];
__device__ float g_csr_w[E_MAX];
__device__ float g_colsum[F_OUT];
__device__ float g_colsumsq[F_OUT];

// ---------------- init / degree / histogram ----------------
__global__ void k_init() {
    int i = blockIdx.x * blockDim.x + threadIdx.x;
    if (i < N_NODES) { g_deg[i] = 1.0f; g_cnt[i] = 0; g_cursor[i] = 0; }
    if (i < F_OUT)   { g_colsum[i] = 0.f; g_colsumsq[i] = 0.f; }
}

// edge_index is int32 on device (JAX x64 disabled downcasts int64).
__global__ void k_deg_hist(const int* __restrict__ ei,
                           const float* __restrict__ ew, int E) {
    int e = blockIdx.x * blockDim.x + threadIdx.x;
    if (e >= E) return;
    int d = ei[E + e];
    atomicAdd(&g_deg[d], ew[e]);
    atomicAdd(&g_cnt[d], 1);
}

// ---------------- scan (+ dinv fused into pass 1) ----------------
__global__ void k_scan1() {
    __shared__ int sm[256];
    int tid = threadIdx.x;
    int i = blockIdx.x * 256 + tid;
    int v = (i < N_NODES) ? g_cnt[i] : 0;
    sm[tid] = v;
    __syncthreads();
    for (int o = 1; o < 256; o <<= 1) {
        int t = (tid >= o) ? sm[tid - o] : 0;
        __syncthreads();
        sm[tid] += t;
        __syncthreads();
    }
    if (i < N_NODES) {
        g_offs[i] = sm[tid] - v;
        g_dinv[i] = rsqrtf(g_deg[i]);   // deg >= 1 (self loop)
    }
    if (tid == 255) g_chunk[blockIdx.x] = sm[tid];
}

__global__ void k_scan2() {
    __shared__ int sm[256];
    int tid = threadIdx.x;
    int v = (tid < NB_SCAN) ? g_chunk[tid] : 0;
    sm[tid] = v;
    __syncthreads();
    for (int o = 1; o < 256; o <<= 1) {
        int t = (tid >= o) ? sm[tid - o] : 0;
        __syncthreads();
        sm[tid] += t;
        __syncthreads();
    }
    if (tid < NB_SCAN) g_chunkbase[tid] = sm[tid] - v;
}

__global__ void k_scan3() {
    int i = blockIdx.x * blockDim.x + threadIdx.x;
    if (i < N_NODES) g_offs[i] += g_chunkbase[i >> 8];
}

// ---------------- CSR fill (by destination) ----------------
__global__ void k_fill(const int* __restrict__ ei,
                       const float* __restrict__ ew, int E) {
    int e = blockIdx.x * blockDim.x + threadIdx.x;
    if (e >= E) return;
    int s = ei[e];
    int d = ei[E + e];
    int slot = g_offs[d] + atomicAdd(&g_cursor[d], 1);
    g_csr_src[slot] = s;
    g_csr_w[slot] = g_dinv[s] * ew[e] * g_dinv[d];
}

// ---------------- tf32 tensor-core GEMM (round-5 proven config) ----------------
// C[M,N] = A[M,K] @ B[K,N], row-major. BM=128, BN=128, BK=32, 256 threads.
// Warp grid 2(M) x 4(N); warp tile 64x32 via m16n8k8 (4 mt x 4 nt).
// cp.async double-buffered; cvt.rna on fragment load (unbiased tf32).

__device__ __forceinline__ uint32_t tf32of(float x) {
    uint32_t y;
    asm("cvt.rna.tf32.f32 %0, %1;" : "=r"(y) : "f"(x));
    return y;
}

__device__ __forceinline__ void mma_tf32(float* c, const uint32_t* a, const uint32_t* b) {
    asm volatile(
        "mma.sync.aligned.m16n8k8.row.col.f32.tf32.tf32.f32 "
        "{%0,%1,%2,%3}, {%4,%5,%6,%7}, {%8,%9}, {%0,%1,%2,%3};"
        : "+f"(c[0]), "+f"(c[1]), "+f"(c[2]), "+f"(c[3])
        : "r"(a[0]), "r"(a[1]), "r"(a[2]), "r"(a[3]), "r"(b[0]), "r"(b[1]));
}

__device__ __forceinline__ void cp_async16(uint32_t dst, const void* src, int src_sz) {
    asm volatile("cp.async.cg.shared.global [%0], [%1], 16, %2;"
                 :: "r"(dst), "l"(src), "r"(src_sz));
}

#define AS_PAD 36   // (4g+q)%32 conflict-free fragment reads
#define BS_PAD 136  // (8q+g)%32 conflict-free fragment reads

__global__ __launch_bounds__(256) void k_tf32gemm(
    const float* __restrict__ A, const float* __restrict__ B,
    float* __restrict__ C, int M, int K, int N) {
    __shared__ float As[2][128][AS_PAD];
    __shared__ float Bs[2][32][BS_PAD];

    const int tid  = threadIdx.x;
    const int bm   = blockIdx.y * 128;
    const int bn   = blockIdx.x * 128;
    const int warp = tid >> 5;
    const int lane = tid & 31;
    const int wm   = warp >> 2;        // 0..1
    const int wn   = warp & 3;         // 0..3
    const int g    = lane >> 2;        // 0..7
    const int q    = lane & 3;         // 0..3

    float c[4][4][4] = {};

    auto load_tiles = [&](int stage, int k0) {
        #pragma unroll
        for (int i = 0; i < 4; i++) {
            int idx = i * 256 + tid;               // 0..1023
            int row = idx >> 3;
            int c4  = (idx & 7) << 2;
            int grow = bm + row;
            int ok = (grow < M) ? 16 : 0;
            const float* src = A + (size_t)(ok ? grow : 0) * K + k0 + c4;
            cp_async16((uint32_t)__cvta_generic_to_shared(&As[stage][row][c4]), src, ok);
        }
        #pragma unroll
        for (int i = 0; i < 4; i++) {
            int idx = i * 256 + tid;
            int row = idx >> 5;                    // 0..31
            int c4  = (idx & 31) << 2;             // 0..124
            const float* src = B + (size_t)(k0 + row) * N + bn + c4;
            cp_async16((uint32_t)__cvta_generic_to_shared(&Bs[stage][row][c4]), src, 16);
        }
        asm volatile("cp.async.commit_group;");
    };

    const int nk = K >> 5;
    load_tiles(0, 0);
    asm volatile("cp.async.wait_group 0;");
    __syncthreads();

    int stage = 0;
    for (int kt = 0; kt < nk; kt++) {
        if (kt + 1 < nk) load_tiles(stage ^ 1, (kt + 1) << 5);

        #pragma unroll
        for (int s = 0; s < 4; s++) {
            const int k = s << 3;
            uint32_t af[4][4], bf[4][2];
            #pragma unroll
            for (int mt = 0; mt < 4; mt++) {
                int r0 = wm * 64 + mt * 16 + g;
                af[mt][0] = tf32of(As[stage][r0    ][k + q]);
                af[mt][1] = tf32of(As[stage][r0 + 8][k + q]);
                af[mt][2] = tf32of(As[stage][r0    ][k + q + 4]);
                af[mt][3] = tf32of(As[stage][r0 + 8][k + q + 4]);
            }
            #pragma unroll
            for (int nt = 0; nt < 4; nt++) {
                int c0 = wn * 32 + nt * 8 + g;
                bf[nt][0] = tf32of(Bs[stage][k + q    ][c0]);
                bf[nt][1] = tf32of(Bs[stage][k + q + 4][c0]);
            }
            #pragma unroll
            for (int mt = 0; mt < 4; mt++)
                #pragma unroll
                for (int nt = 0; nt < 4; nt++)
                    mma_tf32(c[mt][nt], af[mt], bf[nt]);
        }

        asm volatile("cp.async.wait_group 0;");
        __syncthreads();
        stage ^= 1;
    }

    #pragma unroll
    for (int mt = 0; mt < 4; mt++) {
        int row0 = bm + wm * 64 + mt * 16 + g;
        #pragma unroll
        for (int nt = 0; nt < 4; nt++) {
            int col = bn + wn * 32 + nt * 8 + 2 * q;
            if (row0 < M)
                *reinterpret_cast<float2*>(C + (size_t)row0 * N + col) =
                    make_float2(c[mt][nt][0], c[mt][nt][1]);
            if (row0 + 8 < M)
                *reinterpret_cast<float2*>(C + (size_t)(row0 + 8) * N + col) =
                    make_float2(c[mt][nt][2], c[mt][nt][3]);
        }
    }
}

// ---------------- CSR SpMM: warp per dst node, no atomics ----------------
// out[d,:] = dinv[d]^2 * h[d,:] + sum_e w_e * h[src_e,:]; optional relu(v + bias).
template<bool RELU>
__global__ __launch_bounds__(256) void k_spmm(
    const float* __restrict__ h, float* __restrict__ out,
    const float* __restrict__ bias) {
    int node = blockIdx.x * 8 + (threadIdx.x >> 5);
    if (node >= N_NODES) return;
    int lane = threadIdx.x & 31;

    const float4* hrow = reinterpret_cast<const float4*>(h + (size_t)node * F_HID);
    float dd = g_dinv[node]; dd = dd * dd;
    float4 v0 = hrow[lane], v1 = hrow[lane + 32];
    float4 a0 = make_float4(v0.x * dd, v0.y * dd, v0.z * dd, v0.w * dd);
    float4 a1 = make_float4(v1.x * dd, v1.y * dd, v1.z * dd, v1.w * dd);

    int beg = g_offs[node];
    int end = beg + g_cnt[node];
    for (int k = beg; k < end; k++) {
        int s   = g_csr_src[k];
        float w = g_csr_w[k];
        const float4* sr = reinterpret_cast<const float4*>(h + (size_t)s * F_HID);
        float4 s0 = sr[lane], s1 = sr[lane + 32];
        a0.x = fmaf(w, s0.x, a0.x); a0.y = fmaf(w, s0.y, a0.y);
        a0.z = fmaf(w, s0.z, a0.z); a0.w = fmaf(w, s0.w, a0.w);
        a1.x = fmaf(w, s1.x, a1.x); a1.y = fmaf(w, s1.y, a1.y);
        a1.z = fmaf(w, s1.z, a1.z); a1.w = fmaf(w, s1.w, a1.w);
    }
    if (RELU) {
        const float4* b4 = reinterpret_cast<const float4*>(bias);
        float4 bb0 = b4[lane], bb1 = b4[lane + 32];
        a0.x = fmaxf(a0.x + bb0.x, 0.f); a0.y = fmaxf(a0.y + bb0.y, 0.f);
        a0.z = fmaxf(a0.z + bb0.z, 0.f); a0.w = fmaxf(a0.w + bb0.w, 0.f);
        a1.x = fmaxf(a1.x + bb1.x, 0.f); a1.y = fmaxf(a1.y + bb1.y, 0.f);
        a1.z = fmaxf(a1.z + bb1.z, 0.f); a1.w = fmaxf(a1.w + bb1.w, 0.f);
    }
    float4* op = reinterpret_cast<float4*>(out + (size_t)node * F_HID);
    op[lane]      = a0;
    op[lane + 32] = a1;
}

// ---------------- BatchNorm stats (over nodes), bias+relu fused ----------------
__global__ void k_bn_stats(const float* __restrict__ out, const float* __restrict__ b2) {
    int f = threadIdx.x;
    int row0 = blockIdx.x * 64;
    float bias = b2[f];
    float s = 0.f, s2 = 0.f;
    for (int r = 0; r < 64; r++) {
        int row = row0 + r;
        if (row >= N_NODES) break;
        float v = fmaxf(out[(size_t)row * F_OUT + f] + bias, 0.f);
        s += v; s2 += v * v;
    }
    atomicAdd(&g_colsum[f], s);
    atomicAdd(&g_colsumsq[f], s2);
}

// ---------------- final: bias+relu -> BN -> LN, in place; warp per row ----------------
__global__ __launch_bounds__(256) void k_bn_ln(
    float* __restrict__ out, const float* __restrict__ b2,
    const float* __restrict__ bng, const float* __restrict__ bnb,
    const float* __restrict__ lng, const float* __restrict__ lnb) {
    int row  = (int)((blockIdx.x * 256u + threadIdx.x) >> 5);
    int lane = threadIdx.x & 31;
    if (row >= N_NODES) return;
    float* rowp = out + (size_t)row * F_OUT;
    const float invN = 1.0f / (float)N_NODES;
    float y[8];
    float s = 0.f, s2 = 0.f;
    #pragma unroll
    for (int j = 0; j < 8; j++) {
        int f = lane + 32 * j;
        float v   = fmaxf(rowp[f] + b2[f], 0.f);
        float mu  = g_colsum[f] * invN;
        float var = g_colsumsq[f] * invN - mu * mu;
        float yy  = (v - mu) * rsqrtf(var + EPS) * bng[f] + bnb[f];
        y[j] = yy;
        s += yy; s2 += yy * yy;
    }
    #pragma unroll
    for (int o = 16; o; o >>= 1) {
        s  += __shfl_xor_sync(0xffffffffu, s, o);
        s2 += __shfl_xor_sync(0xffffffffu, s2, o);
    }
    float m   = s * (1.0f / F_OUT);
    float var = s2 * (1.0f / F_OUT) - m * m;
    float r   = rsqrtf(var + EPS);
    #pragma unroll
    for (int j = 0; j < 8; j++) {
        int f = lane + 32 * j;
        rowp[f] = (y[j] - m) * r * lng[f] + lnb[f];
    }
}

// ---------------- launch ----------------
extern "C" void kernel_launch(void* const* d_in, const int* in_sizes, int n_in,
                              void* d_out, int out_size) {
    const float* x   = (const float*)d_in[0];
    const int*   ei  = (const int*)d_in[1];     // int32 (JAX x64 disabled)
    const float* ew  = (const float*)d_in[2];
    const float* W1  = (const float*)d_in[3];
    const float* b1  = (const float*)d_in[4];
    const float* W2  = (const float*)d_in[5];
    const float* b2  = (const float*)d_in[6];
    const float* bng = (const float*)d_in[7];
    const float* bnb = (const float*)d_in[8];
    const float* lng = (const float*)d_in[9];
    const float* lnb = (const float*)d_in[10];
    float* out = (float*)d_out;
    const int E = in_sizes[2];

    float *hbuf, *abuf;
    cudaGetSymbolAddress((void**)&hbuf, g_h);
    cudaGetSymbolAddress((void**)&abuf, g_agg);

    const int T = 256;
    k_init<<<(N_NODES + T - 1) / T, T>>>();          // 1
    k_deg_hist<<<(E + T - 1) / T, T>>>(ei, ew, E);   // 2
    k_scan1<<<NB_SCAN, 256>>>();                     // 3 (+dinv)

    // layer 1 GEMM: h1 = x @ W1 — launch slot 4 (ncu profiles the 4th launch)
    {
        dim3 grid(F_HID / 128, (N_NODES + 127) / 128);
        k_tf32gemm<<<grid, 256>>>(x, W1, hbuf, N_NODES, F_IN, F_HID);  // 4 <-- profiled
    }

    k_scan2<<<1, 256>>>();                           // 5
    k_scan3<<<(N_NODES + T - 1) / T, T>>>();         // 6
    k_fill<<<(E + T - 1) / T, T>>>(ei, ew, E);       // 7

    // agg1 = relu(D^-1/2 (A+I) D^-1/2 h1 + b1)
    k_spmm<true><<<N_NODES / 8, 256>>>(hbuf, abuf, b1);   // 8

    // layer 2 GEMM: h2 = agg1 @ W2
    {
        dim3 grid(F_OUT / 128, (N_NODES + 127) / 128);
        k_tf32gemm<<<grid, 256>>>(abuf, W2, hbuf, N_NODES, F_HID, F_OUT);  // 9
    }
    // agg2 into d_out (bias+relu deferred to BN stages)
    k_spmm<false><<<N_NODES / 8, 256>>>(hbuf, out, nullptr);  // 10

    // bias+relu fused into BN stats and finalize
    k_bn_stats<<<(N_NODES + 63) / 64, 256>>>(out, b2);        // 11
    k_bn_ln<<<(N_NODES + 7) / 8, 256>>>(out, b2, bng, bnb, lng, lnb); // 12
}

// round 12
// speedup vs baseline: 1.5169x; 1.5169x over previous
#include <cuda_runtime.h>
#include <cstdint>

#define N_NODES 50000
#define F_IN    1024
#define F_HID   256
#define F_OUT   256
#define EPS     1e-5f
#define E_MAX   1048576
#define NB_SCAN 196        // ceil(50000/256)

// ---------------- scratch (allocation-free: device globals) ----------------
__device__ __align__(256) float g_h[(size_t)N_NODES * F_HID];
__device__ __align__(256) float g_agg[(size_t)N_NODES * F_HID];
__device__ __align__(256) float g_w1r[(size_t)F_IN * F_HID];   // W1, tf32-rounded (same layout)
__device__ __align__(256) float g_w2r[(size_t)F_HID * F_OUT];  // W2, tf32-rounded (same layout)
__device__ float g_deg[N_NODES];
__device__ float g_dinv[N_NODES];
__device__ int   g_cnt[N_NODES];
__device__ int   g_offs[N_NODES];
__device__ int   g_cursor[N_NODES];
__device__ int   g_chunk[256];
__device__ int   g_chunkbase[256];
__device__ int   g_csr_src[E_MAX];
__device__ float g_csr_w[E_MAX];
__device__ float g_colsum[F_OUT];
__device__ float g_colsumsq[F_OUT];

// ---------------- init / degree / histogram ----------------
__global__ void k_init() {
    int i = blockIdx.x * blockDim.x + threadIdx.x;
    if (i < N_NODES) { g_deg[i] = 1.0f; g_cnt[i] = 0; g_cursor[i] = 0; }
    if (i < F_OUT)   { g_colsum[i] = 0.f; g_colsumsq[i] = 0.f; }
}

// edge_index is int32 on device (JAX x64 disabled downcasts int64).
__global__ void k_deg_hist(const int* __restrict__ ei,
                           const float* __restrict__ ew, int E) {
    int e = blockIdx.x * blockDim.x + threadIdx.x;
    if (e >= E) return;
    int d = ei[E + e];
    atomicAdd(&g_deg[d], ew[e]);
    atomicAdd(&g_cnt[d], 1);
}

__global__ void k_dinv() {
    int i = blockIdx.x * blockDim.x + threadIdx.x;
    if (i < N_NODES) g_dinv[i] = rsqrtf(g_deg[i]);  // deg >= 1 (self loop)
}

// ---------------- exclusive scan of g_cnt -> g_offs ----------------
__global__ void k_scan1() {
    __shared__ int sm[256];
    int tid = threadIdx.x;
    int i = blockIdx.x * 256 + tid;
    int v = (i < N_NODES) ? g_cnt[i] : 0;
    sm[tid] = v;
    __syncthreads();
    for (int o = 1; o < 256; o <<= 1) {
        int t = (tid >= o) ? sm[tid - o] : 0;
        __syncthreads();
        sm[tid] += t;
        __syncthreads();
    }
    if (i < N_NODES) g_offs[i] = sm[tid] - v;
    if (tid == 255) g_chunk[blockIdx.x] = sm[tid];
}

__global__ void k_scan2() {
    __shared__ int sm[256];
    int tid = threadIdx.x;
    int v = (tid < NB_SCAN) ? g_chunk[tid] : 0;
    sm[tid] = v;
    __syncthreads();
    for (int o = 1; o < 256; o <<= 1) {
        int t = (tid >= o) ? sm[tid - o] : 0;
        __syncthreads();
        sm[tid] += t;
        __syncthreads();
    }
    if (tid < NB_SCAN) g_chunkbase[tid] = sm[tid] - v;
}

__global__ void k_scan3() {
    int i = blockIdx.x * blockDim.x + threadIdx.x;
    if (i < N_NODES) g_offs[i] += g_chunkbase[i >> 8];
}

// ---------------- CSR fill (by destination) ----------------
__global__ void k_fill(const int* __restrict__ ei,
                       const float* __restrict__ ew, int E) {
    int e = blockIdx.x * blockDim.x + threadIdx.x;
    if (e >= E) return;
    int s = ei[e];
    int d = ei[E + e];
    int slot = g_offs[d] + atomicAdd(&g_cursor[d], 1);
    g_csr_src[slot] = s;
    g_csr_w[slot] = g_dinv[s] * ew[e] * g_dinv[d];
}

// ---------------- weight pre-round to tf32 (RNA), same [K][N] layout ----------------
__device__ __forceinline__ uint32_t tf32of(float x) {
    uint32_t y;
    asm("cvt.rna.tf32.f32 %0, %1;" : "=r"(y) : "f"(x));
    return y;
}

__global__ void k_wround(const float* __restrict__ W, float* __restrict__ Wr, int n) {
    int i = blockIdx.x * blockDim.x + threadIdx.x;
    if (i < n) Wr[i] = __uint_as_float(tf32of(W[i]));
}

// ---------------- tf32 tensor-core GEMM (round-5 proven config) ----------------
// C[M,N] = A[M,K] @ B[K,N], row-major. BM=128, BN=128, BK=32, 256 threads.
// Warp grid 2(M) x 4(N); warp tile 64x32 via m16n8k8 (4 mt x 4 nt).
// cp.async double-buffered. A fragments: cvt.rna at load (unbiased tf32).
// B fragments: NO cvt — B buffer is pre-rounded to tf32 (k_wround), so the
// MMA's internal truncation is the identity. Numerics identical to cvt-at-load.

__device__ __forceinline__ void mma_tf32(float* c, const uint32_t* a, const uint32_t* b) {
    asm volatile(
        "mma.sync.aligned.m16n8k8.row.col.f32.tf32.tf32.f32 "
        "{%0,%1,%2,%3}, {%4,%5,%6,%7}, {%8,%9}, {%0,%1,%2,%3};"
        : "+f"(c[0]), "+f"(c[1]), "+f"(c[2]), "+f"(c[3])
        : "r"(a[0]), "r"(a[1]), "r"(a[2]), "r"(a[3]), "r"(b[0]), "r"(b[1]));
}

__device__ __forceinline__ void cp_async16(uint32_t dst, const void* src, int src_sz) {
    asm volatile("cp.async.cg.shared.global [%0], [%1], 16, %2;"
                 :: "r"(dst), "l"(src), "r"(src_sz));
}

#define AS_PAD 36   // (4g+q)%32 conflict-free fragment reads
#define BS_PAD 136  // (8q+g)%32 conflict-free fragment reads

__global__ __launch_bounds__(256) void k_tf32gemm(
    const float* __restrict__ A, const float* __restrict__ B,
    float* __restrict__ C, int M, int K, int N) {
    __shared__ float As[2][128][AS_PAD];
    __shared__ float Bs[2][32][BS_PAD];

    const int tid  = threadIdx.x;
    const int bm   = blockIdx.y * 128;
    const int bn   = blockIdx.x * 128;
    const int warp = tid >> 5;
    const int lane = tid & 31;
    const int wm   = warp >> 2;        // 0..1
    const int wn   = warp & 3;         // 0..3
    const int g    = lane >> 2;        // 0..7
    const int q    = lane & 3;         // 0..3

    float c[4][4][4] = {};

    auto load_tiles = [&](int stage, int k0) {
        #pragma unroll
        for (int i = 0; i < 4; i++) {
            int idx = i * 256 + tid;               // 0..1023
            int row = idx >> 3;
            int c4  = (idx & 7) << 2;
            int grow = bm + row;
            int ok = (grow < M) ? 16 : 0;
            const float* src = A + (size_t)(ok ? grow : 0) * K + k0 + c4;
            cp_async16((uint32_t)__cvta_generic_to_shared(&As[stage][row][c4]), src, ok);
        }
        #pragma unroll
        for (int i = 0; i < 4; i++) {
            int idx = i * 256 + tid;
            int row = idx >> 5;                    // 0..31
            int c4  = (idx & 31) << 2;             // 0..124
            const float* src = B + (size_t)(k0 + row) * N + bn + c4;
            cp_async16((uint32_t)__cvta_generic_to_shared(&Bs[stage][row][c4]), src, 16);
        }
        asm volatile("cp.async.commit_group;");
    };

    const int nk = K >> 5;
    load_tiles(0, 0);
    asm volatile("cp.async.wait_group 0;");
    __syncthreads();

    int stage = 0;
    for (int kt = 0; kt < nk; kt++) {
        if (kt + 1 < nk) load_tiles(stage ^ 1, (kt + 1) << 5);

        #pragma unroll
        for (int s = 0; s < 4; s++) {
            const int k = s << 3;
            uint32_t af[4][4], bf[4][2];
            #pragma unroll
            for (int mt = 0; mt < 4; mt++) {
                int r0 = wm * 64 + mt * 16 + g;
                af[mt][0] = tf32of(As[stage][r0    ][k + q]);
                af[mt][1] = tf32of(As[stage][r0 + 8][k + q]);
                af[mt][2] = tf32of(As[stage][r0    ][k + q + 4]);
                af[mt][3] = tf32of(As[stage][r0 + 8][k + q + 4]);
            }
            #pragma unroll
            for (int nt = 0; nt < 4; nt++) {
                int c0 = wn * 32 + nt * 8 + g;
                bf[nt][0] = __float_as_uint(Bs[stage][k + q    ][c0]);   // pre-rounded
                bf[nt][1] = __float_as_uint(Bs[stage][k + q + 4][c0]);   // pre-rounded
            }
            #pragma unroll
            for (int mt = 0; mt < 4; mt++)
                #pragma unroll
                for (int nt = 0; nt < 4; nt++)
                    mma_tf32(c[mt][nt], af[mt], bf[nt]);
        }

        asm volatile("cp.async.wait_group 0;");
        __syncthreads();
        stage ^= 1;
    }

    #pragma unroll
    for (int mt = 0; mt < 4; mt++) {
        int row0 = bm + wm * 64 + mt * 16 + g;
        #pragma unroll
        for (int nt = 0; nt < 4; nt++) {
            int col = bn + wn * 32 + nt * 8 + 2 * q;
            if (row0 < M)
                *reinterpret_cast<float2*>(C + (size_t)row0 * N + col) =
                    make_float2(c[mt][nt][0], c[mt][nt][1]);
            if (row0 + 8 < M)
                *reinterpret_cast<float2*>(C + (size_t)(row0 + 8) * N + col) =
                    make_float2(c[mt][nt][2], c[mt][nt][3]);
        }
    }
}

// ---------------- CSR SpMM: warp per dst node, no atomics ----------------
// out[d,:] = dinv[d]^2 * h[d,:] + sum_e w_e * h[src_e,:]; optional relu(v + bias).
template<bool RELU>
__global__ __launch_bounds__(256) void k_spmm(
    const float* __restrict__ h, float* __restrict__ out,
    const float* __restrict__ bias) {
    int node = blockIdx.x * 8 + (threadIdx.x >> 5);
    if (node >= N_NODES) return;
    int lane = threadIdx.x & 31;

    const float4* hrow = reinterpret_cast<const float4*>(h + (size_t)node * F_HID);
    float dd = g_dinv[node]; dd = dd * dd;
    float4 v0 = hrow[lane], v1 = hrow[lane + 32];
    float4 a0 = make_float4(v0.x * dd, v0.y * dd, v0.z * dd, v0.w * dd);
    float4 a1 = make_float4(v1.x * dd, v1.y * dd, v1.z * dd, v1.w * dd);

    int beg = g_offs[node];
    int end = beg + g_cnt[node];
    for (int k = beg; k < end; k++) {
        int s   = g_csr_src[k];
        float w = g_csr_w[k];
        const float4* sr = reinterpret_cast<const float4*>(h + (size_t)s * F_HID);
        float4 s0 = sr[lane], s1 = sr[lane + 32];
        a0.x = fmaf(w, s0.x, a0.x); a0.y = fmaf(w, s0.y, a0.y);
        a0.z = fmaf(w, s0.z, a0.z); a0.w = fmaf(w, s0.w, a0.w);
        a1.x = fmaf(w, s1.x, a1.x); a1.y = fmaf(w, s1.y, a1.y);
        a1.z = fmaf(w, s1.z, a1.z); a1.w = fmaf(w, s1.w, a1.w);
    }
    if (RELU) {
        const float4* b4 = reinterpret_cast<const float4*>(bias);
        float4 bb0 = b4[lane], bb1 = b4[lane + 32];
        a0.x = fmaxf(a0.x + bb0.x, 0.f); a0.y = fmaxf(a0.y + bb0.y, 0.f);
        a0.z = fmaxf(a0.z + bb0.z, 0.f); a0.w = fmaxf(a0.w + bb0.w, 0.f);
        a1.x = fmaxf(a1.x + bb1.x, 0.f); a1.y = fmaxf(a1.y + bb1.y, 0.f);
        a1.z = fmaxf(a1.z + bb1.z, 0.f); a1.w = fmaxf(a1.w + bb1.w, 0.f);
    }
    float4* op = reinterpret_cast<float4*>(out + (size_t)node * F_HID);
    op[lane]      = a0;
    op[lane + 32] = a1;
}

// ---------------- BatchNorm stats (over nodes), bias+relu fused ----------------
__global__ void k_bn_stats(const float* __restrict__ out, const float* __restrict__ b2) {
    int f = threadIdx.x;
    int row0 = blockIdx.x * 64;
    float bias = b2[f];
    float s = 0.f, s2 = 0.f;
    for (int r = 0; r < 64; r++) {
        int row = row0 + r;
        if (row >= N_NODES) break;
        float v = fmaxf(out[(size_t)row * F_OUT + f] + bias, 0.f);
        s += v; s2 += v * v;
    }
    atomicAdd(&g_colsum[f], s);
    atomicAdd(&g_colsumsq[f], s2);
}

// ---------------- final: bias+relu -> BN -> LN, in place; warp per row ----------------
__global__ __launch_bounds__(256) void k_bn_ln(
    float* __restrict__ out, const float* __restrict__ b2,
    const float* __restrict__ bng, const float* __restrict__ bnb,
    const float* __restrict__ lng, const float* __restrict__ lnb) {
    int row  = (int)((blockIdx.x * 256u + threadIdx.x) >> 5);
    int lane = threadIdx.x & 31;
    if (row >= N_NODES) return;
    float* rowp = out + (size_t)row * F_OUT;
    const float invN = 1.0f / (float)N_NODES;
    float y[8];
    float s = 0.f, s2 = 0.f;
    #pragma unroll
    for (int j = 0; j < 8; j++) {
        int f = lane + 32 * j;
        float v   = fmaxf(rowp[f] + b2[f], 0.f);
        float mu  = g_colsum[f] * invN;
        float var = g_colsumsq[f] * invN - mu * mu;
        float yy  = (v - mu) * rsqrtf(var + EPS) * bng[f] + bnb[f];
        y[j] = yy;
        s += yy; s2 += yy * yy;
    }
    #pragma unroll
    for (int o = 16; o; o >>= 1) {
        s  += __shfl_xor_sync(0xffffffffu, s, o);
        s2 += __shfl_xor_sync(0xffffffffu, s2, o);
    }
    float m   = s * (1.0f / F_OUT);
    float var = s2 * (1.0f / F_OUT) - m * m;
    float r   = rsqrtf(var + EPS);
    #pragma unroll
    for (int j = 0; j < 8; j++) {
        int f = lane + 32 * j;
        rowp[f] = (y[j] - m) * r * lng[f] + lnb[f];
    }
}

// ---------------- launch (round-5 exact order + weight-round prep) ----------------
extern "C" void kernel_launch(void* const* d_in, const int* in_sizes, int n_in,
                              void* d_out, int out_size) {
    const float* x   = (const float*)d_in[0];
    const int*   ei  = (const int*)d_in[1];     // int32 (JAX x64 disabled)
    const float* ew  = (const float*)d_in[2];
    const float* W1  = (const float*)d_in[3];
    const float* b1  = (const float*)d_in[4];
    const float* W2  = (const float*)d_in[5];
    const float* b2  = (const float*)d_in[6];
    const float* bng = (const float*)d_in[7];
    const float* bnb = (const float*)d_in[8];
    const float* lng = (const float*)d_in[9];
    const float* lnb = (const float*)d_in[10];
    float* out = (float*)d_out;
    const int E = in_sizes[2];

    float *hbuf, *abuf, *w1r, *w2r;
    cudaGetSymbolAddress((void**)&hbuf, g_h);
    cudaGetSymbolAddress((void**)&abuf, g_agg);
    cudaGetSymbolAddress((void**)&w1r, g_w1r);
    cudaGetSymbolAddress((void**)&w2r, g_w2r);

    const int T = 256;
    // graph prep (round-5 order)
    k_init<<<(N_NODES + T - 1) / T, T>>>();
    k_deg_hist<<<(E + T - 1) / T, T>>>(ei, ew, E);
    k_dinv<<<(N_NODES + T - 1) / T, T>>>();
    k_scan1<<<NB_SCAN, 256>>>();
    k_scan2<<<1, 256>>>();
    k_scan3<<<(N_NODES + T - 1) / T, T>>>();
    k_fill<<<(E + T - 1) / T, T>>>(ei, ew, E);

    // weight pre-round to tf32 (tiny)
    k_wround<<<(F_IN * F_HID + T - 1) / T, T>>>(W1, w1r, F_IN * F_HID);
    k_wround<<<(F_HID * F_OUT + T - 1) / T, T>>>(W2, w2r, F_HID * F_OUT);

    // layer 1: h1 = x @ W1 ; agg1 = relu(D^-1/2 (A+I) D^-1/2 h1 + b1)
    {
        dim3 grid(F_HID / 128, (N_NODES + 127) / 128);
        k_tf32gemm<<<grid, 256>>>(x, w1r, hbuf, N_NODES, F_IN, F_HID);
    }
    k_spmm<true><<<N_NODES / 8, 256>>>(hbuf, abuf, b1);

    // layer 2: h2 = agg1 @ W2 ; agg2 into d_out (bias+relu deferred to BN stage)
    {
        dim3 grid(F_OUT / 128, (N_NODES + 127) / 128);
        k_tf32gemm<<<grid, 256>>>(abuf, w2r, hbuf, N_NODES, F_HID, F_OUT);
    }
    k_spmm<false><<<N_NODES / 8, 256>>>(hbuf, out, nullptr);

    // bias+relu fused into BN stats and finalize
    k_bn_stats<<<(N_NODES + 63) / 64, 256>>>(out, b2);
    k_bn_ln<<<(N_NODES + 7) / 8, 256>>>(out, b2, bng, bnb, lng, lnb);
}

// round 13
// speedup vs baseline: 1.6188x; 1.0672x over previous
#include <cuda_runtime.h>
#include <cuda_fp16.h>
#include <cstdint>

#define N_NODES 50000
#define F_IN    1024
#define F_HID   256
#define F_OUT   256
#define EPS     1e-5f
#define E_MAX   1048576
#define NB_SCAN 196        // ceil(50000/256)

// ---------------- scratch (allocation-free: device globals) ----------------
__device__ __align__(256) float  g_h[(size_t)N_NODES * F_HID];     // GEMM outputs (fp32)
__device__ __align__(256) __half g_xh[(size_t)N_NODES * F_IN];     // x in fp16
__device__ __align__(256) __half g_aggh[(size_t)N_NODES * F_HID];  // agg1 in fp16
__device__ __align__(256) __half g_wh1[(size_t)F_HID * F_IN];      // W1^T fp16 [n][k]
__device__ __align__(256) __half g_wh2[(size_t)F_OUT * F_HID];     // W2^T fp16 [n][k]
__device__ float g_deg[N_NODES];
__device__ float g_dinv[N_NODES];
__device__ int   g_cnt[N_NODES];
__device__ int   g_offs[N_NODES];
__device__ int   g_cursor[N_NODES];
__device__ int   g_chunk[256];
__device__ int   g_chunkbase[256];
__device__ int   g_csr_src[E_MAX];
__device__ float g_csr_w[E_MAX];
__device__ float g_colsum[F_OUT];
__device__ float g_colsumsq[F_OUT];

// ---------------- init / degree / histogram ----------------
__global__ void k_init() {
    int i = blockIdx.x * blockDim.x + threadIdx.x;
    if (i < N_NODES) { g_deg[i] = 1.0f; g_cnt[i] = 0; g_cursor[i] = 0; }
    if (i < F_OUT)   { g_colsum[i] = 0.f; g_colsumsq[i] = 0.f; }
}

// edge_index is int32 on device (JAX x64 disabled downcasts int64).
__global__ void k_deg_hist(const int* __restrict__ ei,
                           const float* __restrict__ ew, int E) {
    int e = blockIdx.x * blockDim.x + threadIdx.x;
    if (e >= E) return;
    int d = ei[E + e];
    atomicAdd(&g_deg[d], ew[e]);
    atomicAdd(&g_cnt[d], 1);
}

__global__ void k_dinv() {
    int i = blockIdx.x * blockDim.x + threadIdx.x;
    if (i < N_NODES) g_dinv[i] = rsqrtf(g_deg[i]);  // deg >= 1 (self loop)
}

// ---------------- exclusive scan of g_cnt -> g_offs ----------------
__global__ void k_scan1() {
    __shared__ int sm[256];
    int tid = threadIdx.x;
    int i = blockIdx.x * 256 + tid;
    int v = (i < N_NODES) ? g_cnt[i] : 0;
    sm[tid] = v;
    __syncthreads();
    for (int o = 1; o < 256; o <<= 1) {
        int t = (tid >= o) ? sm[tid - o] : 0;
        __syncthreads();
        sm[tid] += t;
        __syncthreads();
    }
    if (i < N_NODES) g_offs[i] = sm[tid] - v;
    if (tid == 255) g_chunk[blockIdx.x] = sm[tid];
}

__global__ void k_scan2() {
    __shared__ int sm[256];
    int tid = threadIdx.x;
    int v = (tid < NB_SCAN) ? g_chunk[tid] : 0;
    sm[tid] = v;
    __syncthreads();
    for (int o = 1; o < 256; o <<= 1) {
        int t = (tid >= o) ? sm[tid - o] : 0;
        __syncthreads();
        sm[tid] += t;
        __syncthreads();
    }
    if (tid < NB_SCAN) g_chunkbase[tid] = sm[tid] - v;
}

__global__ void k_scan3() {
    int i = blockIdx.x * blockDim.x + threadIdx.x;
    if (i < N_NODES) g_offs[i] += g_chunkbase[i >> 8];
}

// ---------------- CSR fill (by destination) ----------------
__global__ void k_fill(const int* __restrict__ ei,
                       const float* __restrict__ ew, int E) {
    int e = blockIdx.x * blockDim.x + threadIdx.x;
    if (e >= E) return;
    int s = ei[e];
    int d = ei[E + e];
    int slot = g_offs[d] + atomicAdd(&g_cursor[d], 1);
    g_csr_src[slot] = s;
    g_csr_w[slot] = g_dinv[s] * ew[e] * g_dinv[d];
}

// ---------------- fp16 conversions ----------------
// x -> fp16, 8 floats per thread
__global__ void k_xhalf(const float* __restrict__ x, __half* __restrict__ xh, int n8) {
    int i = blockIdx.x * blockDim.x + threadIdx.x;
    if (i >= n8) return;
    const float4* xp = reinterpret_cast<const float4*>(x) + 2 * (size_t)i;
    float4 v0 = xp[0], v1 = xp[1];
    __half2 h0 = __floats2half2_rn(v0.x, v0.y);
    __half2 h1 = __floats2half2_rn(v0.z, v0.w);
    __half2 h2 = __floats2half2_rn(v1.x, v1.y);
    __half2 h3 = __floats2half2_rn(v1.z, v1.w);
    uint4 u;
    u.x = *reinterpret_cast<uint32_t*>(&h0);
    u.y = *reinterpret_cast<uint32_t*>(&h1);
    u.z = *reinterpret_cast<uint32_t*>(&h2);
    u.w = *reinterpret_cast<uint32_t*>(&h3);
    reinterpret_cast<uint4*>(xh)[i] = u;
}

// W[k][n] -> Wh[n][k] fp16 (transpose + convert)
__global__ void k_wh(const float* __restrict__ W, __half* __restrict__ Wh, int K, int N) {
    int idx = blockIdx.x * blockDim.x + threadIdx.x;
    if (idx >= K * N) return;
    int n = idx / K, k = idx - n * K;
    Wh[idx] = __float2half(W[(size_t)k * N + n]);
}

// ---------------- fp16 tensor-core GEMM ----------------
// C[M,N] = A[M,K] @ Bt[N,K]^T (fp16 in, fp32 out). BM=128, BN=128, BK=32,
// 256 threads, warp grid 2(M) x 4(N), warp tile 64x32 via m16n8k16 (4mt x 4nt).
// Bt is [n][k] so every B fragment is a contiguous half2. A fragments likewise.
// Row pad 40 halves -> LDS banks (20g+q)%32 all distinct (conflict-free).

__device__ __forceinline__ void mma_f16(float* c, const uint32_t* a, const uint32_t* b) {
    asm volatile(
        "mma.sync.aligned.m16n8k16.row.col.f32.f16.f16.f32 "
        "{%0,%1,%2,%3}, {%4,%5,%6,%7}, {%8,%9}, {%0,%1,%2,%3};"
        : "+f"(c[0]), "+f"(c[1]), "+f"(c[2]), "+f"(c[3])
        : "r"(a[0]), "r"(a[1]), "r"(a[2]), "r"(a[3]), "r"(b[0]), "r"(b[1]));
}

__device__ __forceinline__ void cp_async16(uint32_t dst, const void* src, int src_sz) {
    asm volatile("cp.async.cg.shared.global [%0], [%1], 16, %2;"
                 :: "r"(dst), "l"(src), "r"(src_sz));
}

#define HPAD 40   // halves per row (32 data + 8 pad)

__global__ __launch_bounds__(256) void k_hgemm(
    const __half* __restrict__ A, const __half* __restrict__ Bt,
    float* __restrict__ C, int M, int K, int N) {
    __shared__ __half Ah[2][128][HPAD];   // 20 KB
    __shared__ __half Bh[2][128][HPAD];   // 20 KB

    const int tid  = threadIdx.x;
    const int bm   = blockIdx.y * 128;
    const int bn   = blockIdx.x * 128;
    const int warp = tid >> 5;
    const int lane = tid & 31;
    const int wm   = warp >> 2;        // 0..1
    const int wn   = warp & 3;         // 0..3
    const int g    = lane >> 2;        // 0..7
    const int q    = lane & 3;         // 0..3

    float c[4][4][4] = {};

    auto load_tiles = [&](int stage, int k0) {
        #pragma unroll
        for (int i = 0; i < 2; i++) {              // A: 128 rows x 32 halves = 512 x 16B
            int idx = i * 256 + tid;               // 0..511
            int row = idx >> 2;
            int c8  = (idx & 3) << 3;
            int grow = bm + row;
            int ok = (grow < M) ? 16 : 0;
            const __half* src = A + (size_t)(ok ? grow : 0) * K + k0 + c8;
            cp_async16((uint32_t)__cvta_generic_to_shared(&Ah[stage][row][c8]), src, ok);
        }
        #pragma unroll
        for (int i = 0; i < 2; i++) {              // B: 128 n-rows x 32 halves
            int idx = i * 256 + tid;
            int row = idx >> 2;
            int c8  = (idx & 3) << 3;
            const __half* src = Bt + (size_t)(bn + row) * K + k0 + c8;
            cp_async16((uint32_t)__cvta_generic_to_shared(&Bh[stage][row][c8]), src, 16);
        }
        asm volatile("cp.async.commit_group;");
    };

    const int nk = K >> 5;
    load_tiles(0, 0);
    asm volatile("cp.async.wait_group 0;");
    __syncthreads();

    int stage = 0;
    for (int kt = 0; kt < nk; kt++) {
        if (kt + 1 < nk) load_tiles(stage ^ 1, (kt + 1) << 5);

        #pragma unroll
        for (int ks = 0; ks < 2; ks++) {
            const int kb = ks << 4;                // 0 or 16
            uint32_t af[4][4], bf[4][2];
            #pragma unroll
            for (int mt = 0; mt < 4; mt++) {
                int r0 = wm * 64 + mt * 16 + g;
                af[mt][0] = *reinterpret_cast<const uint32_t*>(&Ah[stage][r0    ][kb + 2 * q]);
                af[mt][1] = *reinterpret_cast<const uint32_t*>(&Ah[stage][r0 + 8][kb + 2 * q]);
                af[mt][2] = *reinterpret_cast<const uint32_t*>(&Ah[stage][r0    ][kb + 2 * q + 8]);
                af[mt][3] = *reinterpret_cast<const uint32_t*>(&Ah[stage][r0 + 8][kb + 2 * q + 8]);
            }
            #pragma unroll
            for (int nt = 0; nt < 4; nt++) {
                int c0 = wn * 32 + nt * 8 + g;
                bf[nt][0] = *reinterpret_cast<const uint32_t*>(&Bh[stage][c0][kb + 2 * q]);
                bf[nt][1] = *reinterpret_cast<const uint32_t*>(&Bh[stage][c0][kb + 2 * q + 8]);
            }
            #pragma unroll
            for (int mt = 0; mt < 4; mt++)
                #pragma unroll
                for (int nt = 0; nt < 4; nt++)
                    mma_f16(c[mt][nt], af[mt], bf[nt]);
        }

        asm volatile("cp.async.wait_group 0;");
        __syncthreads();
        stage ^= 1;
    }

    #pragma unroll
    for (int mt = 0; mt < 4; mt++) {
        int row0 = bm + wm * 64 + mt * 16 + g;
        #pragma unroll
        for (int nt = 0; nt < 4; nt++) {
            int col = bn + wn * 32 + nt * 8 + 2 * q;
            if (row0 < M)
                *reinterpret_cast<float2*>(C + (size_t)row0 * N + col) =
                    make_float2(c[mt][nt][0], c[mt][nt][1]);
            if (row0 + 8 < M)
                *reinterpret_cast<float2*>(C + (size_t)(row0 + 8) * N + col) =
                    make_float2(c[mt][nt][2], c[mt][nt][3]);
        }
    }
}

// ---------------- CSR SpMM (fp32 accumulate), two epilogues ----------------
// layer 1: relu(v + b1) -> fp16 agg (feeds GEMM2)
__global__ __launch_bounds__(256) void k_spmm_h(
    const float* __restrict__ h, __half* __restrict__ out,
    const float* __restrict__ bias) {
    int node = blockIdx.x * 8 + (threadIdx.x >> 5);
    if (node >= N_NODES) return;
    int lane = threadIdx.x & 31;

    const float4* hrow = reinterpret_cast<const float4*>(h + (size_t)node * F_HID);
    float dd = g_dinv[node]; dd = dd * dd;
    float4 v0 = hrow[lane], v1 = hrow[lane + 32];
    float4 a0 = make_float4(v0.x * dd, v0.y * dd, v0.z * dd, v0.w * dd);
    float4 a1 = make_float4(v1.x * dd, v1.y * dd, v1.z * dd, v1.w * dd);

    int beg = g_offs[node];
    int end = beg + g_cnt[node];
    for (int k = beg; k < end; k++) {
        int s   = g_csr_src[k];
        float w = g_csr_w[k];
        const float4* sr = reinterpret_cast<const float4*>(h + (size_t)s * F_HID);
        float4 s0 = sr[lane], s1 = sr[lane + 32];
        a0.x = fmaf(w, s0.x, a0.x); a0.y = fmaf(w, s0.y, a0.y);
        a0.z = fmaf(w, s0.z, a0.z); a0.w = fmaf(w, s0.w, a0.w);
        a1.x = fmaf(w, s1.x, a1.x); a1.y = fmaf(w, s1.y, a1.y);
        a1.z = fmaf(w, s1.z, a1.z); a1.w = fmaf(w, s1.w, a1.w);
    }
    const float4* b4 = reinterpret_cast<const float4*>(bias);
    float4 bb0 = b4[lane], bb1 = b4[lane + 32];
    a0.x = fmaxf(a0.x + bb0.x, 0.f); a0.y = fmaxf(a0.y + bb0.y, 0.f);
    a0.z = fmaxf(a0.z + bb0.z, 0.f); a0.w = fmaxf(a0.w + bb0.w, 0.f);
    a1.x = fmaxf(a1.x + bb1.x, 0.f); a1.y = fmaxf(a1.y + bb1.y, 0.f);
    a1.z = fmaxf(a1.z + bb1.z, 0.f); a1.w = fmaxf(a1.w + bb1.w, 0.f);

    __half2 h0 = __floats2half2_rn(a0.x, a0.y);
    __half2 h1 = __floats2half2_rn(a0.z, a0.w);
    __half2 h2 = __floats2half2_rn(a1.x, a1.y);
    __half2 h3 = __floats2half2_rn(a1.z, a1.w);
    uint2 u0, u1;
    u0.x = *reinterpret_cast<uint32_t*>(&h0); u0.y = *reinterpret_cast<uint32_t*>(&h1);
    u1.x = *reinterpret_cast<uint32_t*>(&h2); u1.y = *reinterpret_cast<uint32_t*>(&h3);
    uint2* op = reinterpret_cast<uint2*>(out + (size_t)node * F_HID);
    op[lane]      = u0;
    op[lane + 32] = u1;
}

// layer 2: plain fp32 out (bias+relu deferred to BN stages)
__global__ __launch_bounds__(256) void k_spmm(
    const float* __restrict__ h, float* __restrict__ out) {
    int node = blockIdx.x * 8 + (threadIdx.x >> 5);
    if (node >= N_NODES) return;
    int lane = threadIdx.x & 31;

    const float4* hrow = reinterpret_cast<const float4*>(h + (size_t)node * F_HID);
    float dd = g_dinv[node]; dd = dd * dd;
    float4 v0 = hrow[lane], v1 = hrow[lane + 32];
    float4 a0 = make_float4(v0.x * dd, v0.y * dd, v0.z * dd, v0.w * dd);
    float4 a1 = make_float4(v1.x * dd, v1.y * dd, v1.z * dd, v1.w * dd);

    int beg = g_offs[node];
    int end = beg + g_cnt[node];
    for (int k = beg; k < end; k++) {
        int s   = g_csr_src[k];
        float w = g_csr_w[k];
        const float4* sr = reinterpret_cast<const float4*>(h + (size_t)s * F_HID);
        float4 s0 = sr[lane], s1 = sr[lane + 32];
        a0.x = fmaf(w, s0.x, a0.x); a0.y = fmaf(w, s0.y, a0.y);
        a0.z = fmaf(w, s0.z, a0.z); a0.w = fmaf(w, s0.w, a0.w);
        a1.x = fmaf(w, s1.x, a1.x); a1.y = fmaf(w, s1.y, a1.y);
        a1.z = fmaf(w, s1.z, a1.z); a1.w = fmaf(w, s1.w, a1.w);
    }
    float4* op = reinterpret_cast<float4*>(out + (size_t)node * F_HID);
    op[lane]      = a0;
    op[lane + 32] = a1;
}

// ---------------- BatchNorm stats (over nodes), bias+relu fused ----------------
__global__ void k_bn_stats(const float* __restrict__ out, const float* __restrict__ b2) {
    int f = threadIdx.x;
    int row0 = blockIdx.x * 64;
    float bias = b2[f];
    float s = 0.f, s2 = 0.f;
    for (int r = 0; r < 64; r++) {
        int row = row0 + r;
        if (row >= N_NODES) break;
        float v = fmaxf(out[(size_t)row * F_OUT + f] + bias, 0.f);
        s += v; s2 += v * v;
    }
    atomicAdd(&g_colsum[f], s);
    atomicAdd(&g_colsumsq[f], s2);
}

// ---------------- final: bias+relu -> BN -> LN, in place; warp per row ----------------
__global__ __launch_bounds__(256) void k_bn_ln(
    float* __restrict__ out, const float* __restrict__ b2,
    const float* __restrict__ bng, const float* __restrict__ bnb,
    const float* __restrict__ lng, const float* __restrict__ lnb) {
    int row  = (int)((blockIdx.x * 256u + threadIdx.x) >> 5);
    int lane = threadIdx.x & 31;
    if (row >= N_NODES) return;
    float* rowp = out + (size_t)row * F_OUT;
    const float invN = 1.0f / (float)N_NODES;
    float y[8];
    float s = 0.f, s2 = 0.f;
    #pragma unroll
    for (int j = 0; j < 8; j++) {
        int f = lane + 32 * j;
        float v   = fmaxf(rowp[f] + b2[f], 0.f);
        float mu  = g_colsum[f] * invN;
        float var = g_colsumsq[f] * invN - mu * mu;
        float yy  = (v - mu) * rsqrtf(var + EPS) * bng[f] + bnb[f];
        y[j] = yy;
        s += yy; s2 += yy * yy;
    }
    #pragma unroll
    for (int o = 16; o; o >>= 1) {
        s  += __shfl_xor_sync(0xffffffffu, s, o);
        s2 += __shfl_xor_sync(0xffffffffu, s2, o);
    }
    float m   = s * (1.0f / F_OUT);
    float var = s2 * (1.0f / F_OUT) - m * m;
    float r   = rsqrtf(var + EPS);
    #pragma unroll
    for (int j = 0; j < 8; j++) {
        int f = lane + 32 * j;
        rowp[f] = (y[j] - m) * r * lng[f] + lnb[f];
    }
}

// ---------------- launch (round-5 proven prep order) ----------------
extern "C" void kernel_launch(void* const* d_in, const int* in_sizes, int n_in,
                              void* d_out, int out_size) {
    const float* x   = (const float*)d_in[0];
    const int*   ei  = (const int*)d_in[1];     // int32 (JAX x64 disabled)
    const float* ew  = (const float*)d_in[2];
    const float* W1  = (const float*)d_in[3];
    const float* b1  = (const float*)d_in[4];
    const float* W2  = (const float*)d_in[5];
    const float* b2  = (const float*)d_in[6];
    const float* bng = (const float*)d_in[7];
    const float* bnb = (const float*)d_in[8];
    const float* lng = (const float*)d_in[9];
    const float* lnb = (const float*)d_in[10];
    float* out = (float*)d_out;
    const int E = in_sizes[2];

    float  *hbuf;
    __half *xh, *aggh, *wh1, *wh2;
    cudaGetSymbolAddress((void**)&hbuf, g_h);
    cudaGetSymbolAddress((void**)&xh,   g_xh);
    cudaGetSymbolAddress((void**)&aggh, g_aggh);
    cudaGetSymbolAddress((void**)&wh1,  g_wh1);
    cudaGetSymbolAddress((void**)&wh2,  g_wh2);

    const int T = 256;
    // graph prep (round-5 order)
    k_init<<<(N_NODES + T - 1) / T, T>>>();
    k_deg_hist<<<(E + T - 1) / T, T>>>(ei, ew, E);
    k_dinv<<<(N_NODES + T - 1) / T, T>>>();
    k_scan1<<<NB_SCAN, 256>>>();
    k_scan2<<<1, 256>>>();
    k_scan3<<<(N_NODES + T - 1) / T, T>>>();
    k_fill<<<(E + T - 1) / T, T>>>(ei, ew, E);

    // fp16 conversions
    k_xhalf<<<(N_NODES * F_IN / 8 + T - 1) / T, T>>>(x, xh, N_NODES * F_IN / 8);
    k_wh<<<(F_IN * F_HID + T - 1) / T, T>>>(W1, wh1, F_IN, F_HID);
    k_wh<<<(F_HID * F_OUT + T - 1) / T, T>>>(W2, wh2, F_HID, F_OUT);

    // layer 1: h1 = x @ W1 (fp16 mma, fp32 accum)
    {
        dim3 grid(F_HID / 128, (N_NODES + 127) / 128);
        k_hgemm<<<grid, 256>>>(xh, wh1, hbuf, N_NODES, F_IN, F_HID);
    }
    // agg1 = fp16(relu(D^-1/2 (A+I) D^-1/2 h1 + b1))
    k_spmm_h<<<N_NODES / 8, 256>>>(hbuf, aggh, b1);

    // layer 2: h2 = agg1 @ W2
    {
        dim3 grid(F_OUT / 128, (N_NODES + 127) / 128);
        k_hgemm<<<grid, 256>>>(aggh, wh2, hbuf, N_NODES, F_HID, F_OUT);
    }
    // agg2 into d_out
    k_spmm<<<N_NODES / 8, 256>>>(hbuf, out);

    // bias+relu fused into BN stats and finalize
    k_bn_stats<<<(N_NODES + 63) / 64, 256>>>(out, b2);
    k_bn_ln<<<(N_NODES + 7) / 8, 256>>>(out, b2, bng, bnb, lng, lnb);
}

// round 16
// speedup vs baseline: 1.7791x; 1.0990x over previous
#include <cuda_runtime.h>
#include <cuda_fp16.h>
#include <cstdint>

#define N_NODES 50000
#define F_IN    1024
#define F_HID   256
#define F_OUT   256
#define EPS     1e-5f
#define E_MAX   1048576
#define NB_SCAN 196        // ceil(50000/256)

// ---------------- scratch (allocation-free: device globals) ----------------
__device__ __align__(256) __half g_hh[(size_t)N_NODES * F_HID];    // GEMM outputs (fp16)
__device__ __align__(256) __half g_xh[(size_t)N_NODES * F_IN];     // x in fp16
__device__ __align__(256) __half g_aggh[(size_t)N_NODES * F_HID];  // agg1 in fp16
__device__ __align__(256) __half g_wh1[(size_t)F_HID * F_IN];      // W1^T fp16 [n][k]
__device__ __align__(256) __half g_wh2[(size_t)F_OUT * F_HID];     // W2^T fp16 [n][k]
__device__ float g_deg[N_NODES];
__device__ float g_dinv[N_NODES];
__device__ int   g_cnt[N_NODES];
__device__ int   g_offs[N_NODES];
__device__ int   g_cursor[N_NODES];
__device__ int   g_chunk[256];
__device__ int   g_chunkbase[256];
__device__ __align__(256) int2 g_csr[E_MAX];    // {src, __float_as_int(w)}
__device__ float g_colsum[F_OUT];
__device__ float g_colsumsq[F_OUT];

// ---------------- init / degree / histogram ----------------
__global__ void k_init() {
    int i = blockIdx.x * blockDim.x + threadIdx.x;
    if (i < N_NODES) { g_deg[i] = 1.0f; g_cnt[i] = 0; g_cursor[i] = 0; }
    if (i < F_OUT)   { g_colsum[i] = 0.f; g_colsumsq[i] = 0.f; }
}

// edge_index is int32 on device (JAX x64 disabled downcasts int64).
__global__ void k_deg_hist(const int* __restrict__ ei,
                           const float* __restrict__ ew, int E) {
    int e = blockIdx.x * blockDim.x + threadIdx.x;
    if (e >= E) return;
    int d = ei[E + e];
    atomicAdd(&g_deg[d], ew[e]);
    atomicAdd(&g_cnt[d], 1);
}

__global__ void k_dinv() {
    int i = blockIdx.x * blockDim.x + threadIdx.x;
    if (i < N_NODES) g_dinv[i] = rsqrtf(g_deg[i]);  // deg >= 1 (self loop)
}

// ---------------- exclusive scan of g_cnt -> g_offs ----------------
__global__ void k_scan1() {
    __shared__ int sm[256];
    int tid = threadIdx.x;
    int i = blockIdx.x * 256 + tid;
    int v = (i < N_NODES) ? g_cnt[i] : 0;
    sm[tid] = v;
    __syncthreads();
    for (int o = 1; o < 256; o <<= 1) {
        int t = (tid >= o) ? sm[tid - o] : 0;
        __syncthreads();
        sm[tid] += t;
        __syncthreads();
    }
    if (i < N_NODES) g_offs[i] = sm[tid] - v;
    if (tid == 255) g_chunk[blockIdx.x] = sm[tid];
}

__global__ void k_scan2() {
    __shared__ int sm[256];
    int tid = threadIdx.x;
    int v = (tid < NB_SCAN) ? g_chunk[tid] : 0;
    sm[tid] = v;
    __syncthreads();
    for (int o = 1; o < 256; o <<= 1) {
        int t = (tid >= o) ? sm[tid - o] : 0;
        __syncthreads();
        sm[tid] += t;
        __syncthreads();
    }
    if (tid < NB_SCAN) g_chunkbase[tid] = sm[tid] - v;
}

__global__ void k_scan3() {
    int i = blockIdx.x * blockDim.x + threadIdx.x;
    if (i < N_NODES) g_offs[i] += g_chunkbase[i >> 8];
}

// ---------------- CSR fill (by destination), packed {src, w} ----------------
__global__ void k_fill(const int* __restrict__ ei,
                       const float* __restrict__ ew, int E) {
    int e = blockIdx.x * blockDim.x + threadIdx.x;
    if (e >= E) return;
    int s = ei[e];
    int d = ei[E + e];
    int slot = g_offs[d] + atomicAdd(&g_cursor[d], 1);
    float w = g_dinv[s] * ew[e] * g_dinv[d];
    g_csr[slot] = make_int2(s, __float_as_int(w));
}

// ---------------- fp16 conversions ----------------
__global__ void k_xhalf(const float* __restrict__ x, __half* __restrict__ xh, int n8) {
    int i = blockIdx.x * blockDim.x + threadIdx.x;
    if (i >= n8) return;
    const float4* xp = reinterpret_cast<const float4*>(x) + 2 * (size_t)i;
    float4 v0 = xp[0], v1 = xp[1];
    __half2 h0 = __floats2half2_rn(v0.x, v0.y);
    __half2 h1 = __floats2half2_rn(v0.z, v0.w);
    __half2 h2 = __floats2half2_rn(v1.x, v1.y);
    __half2 h3 = __floats2half2_rn(v1.z, v1.w);
    uint4 u;
    u.x = *reinterpret_cast<uint32_t*>(&h0);
    u.y = *reinterpret_cast<uint32_t*>(&h1);
    u.z = *reinterpret_cast<uint32_t*>(&h2);
    u.w = *reinterpret_cast<uint32_t*>(&h3);
    reinterpret_cast<uint4*>(xh)[i] = u;
}

// W[k][n] -> Wh[n][k] fp16 (transpose + convert)
__global__ void k_wh(const float* __restrict__ W, __half* __restrict__ Wh, int K, int N) {
    int idx = blockIdx.x * blockDim.x + threadIdx.x;
    if (idx >= K * N) return;
    int n = idx / K, k = idx - n * K;
    Wh[idx] = __float2half(W[(size_t)k * N + n]);
}

// ---------------- fp16 tensor-core GEMM (fp16 out) ----------------
// C[M,N] = A[M,K] @ Bt[N,K]^T. BM=128, BN=128, BK=32, 256 threads,
// warp grid 2(M) x 4(N), warp tile 64x32 via m16n8k16. fp32 accum, fp16 store.
__device__ __forceinline__ void mma_f16(float* c, const uint32_t* a, const uint32_t* b) {
    asm volatile(
        "mma.sync.aligned.m16n8k16.row.col.f32.f16.f16.f32 "
        "{%0,%1,%2,%3}, {%4,%5,%6,%7}, {%8,%9}, {%0,%1,%2,%3};"
        : "+f"(c[0]), "+f"(c[1]), "+f"(c[2]), "+f"(c[3])
        : "r"(a[0]), "r"(a[1]), "r"(a[2]), "r"(a[3]), "r"(b[0]), "r"(b[1]));
}

__device__ __forceinline__ void cp_async16(uint32_t dst, const void* src, int src_sz) {
    asm volatile("cp.async.cg.shared.global [%0], [%1], 16, %2;"
                 :: "r"(dst), "l"(src), "r"(src_sz));
}

#define HPAD 40   // halves per row (32 data + 8 pad): conflict-free fragment LDS

__global__ __launch_bounds__(256) void k_hgemm(
    const __half* __restrict__ A, const __half* __restrict__ Bt,
    __half* __restrict__ C, int M, int K, int N) {
    __shared__ __half Ah[2][128][HPAD];
    __shared__ __half Bh[2][128][HPAD];

    const int tid  = threadIdx.x;
    const int bm   = blockIdx.y * 128;
    const int bn   = blockIdx.x * 128;
    const int warp = tid >> 5;
    const int lane = tid & 31;
    const int wm   = warp >> 2;
    const int wn   = warp & 3;
    const int g    = lane >> 2;
    const int q    = lane & 3;

    float c[4][4][4] = {};

    auto load_tiles = [&](int stage, int k0) {
        #pragma unroll
        for (int i = 0; i < 2; i++) {
            int idx = i * 256 + tid;
            int row = idx >> 2;
            int c8  = (idx & 3) << 3;
            int grow = bm + row;
            int ok = (grow < M) ? 16 : 0;
            const __half* src = A + (size_t)(ok ? grow : 0) * K + k0 + c8;
            cp_async16((uint32_t)__cvta_generic_to_shared(&Ah[stage][row][c8]), src, ok);
        }
        #pragma unroll
        for (int i = 0; i < 2; i++) {
            int idx = i * 256 + tid;
            int row = idx >> 2;
            int c8  = (idx & 3) << 3;
            const __half* src = Bt + (size_t)(bn + row) * K + k0 + c8;
            cp_async16((uint32_t)__cvta_generic_to_shared(&Bh[stage][row][c8]), src, 16);
        }
        asm volatile("cp.async.commit_group;");
    };

    const int nk = K >> 5;
    load_tiles(0, 0);
    asm volatile("cp.async.wait_group 0;");
    __syncthreads();

    int stage = 0;
    for (int kt = 0; kt < nk; kt++) {
        if (kt + 1 < nk) load_tiles(stage ^ 1, (kt + 1) << 5);

        #pragma unroll
        for (int ks = 0; ks < 2; ks++) {
            const int kb = ks << 4;
            uint32_t af[4][4], bf[4][2];
            #pragma unroll
            for (int mt = 0; mt < 4; mt++) {
                int r0 = wm * 64 + mt * 16 + g;
                af[mt][0] = *reinterpret_cast<const uint32_t*>(&Ah[stage][r0    ][kb + 2 * q]);
                af[mt][1] = *reinterpret_cast<const uint32_t*>(&Ah[stage][r0 + 8][kb + 2 * q]);
                af[mt][2] = *reinterpret_cast<const uint32_t*>(&Ah[stage][r0    ][kb + 2 * q + 8]);
                af[mt][3] = *reinterpret_cast<const uint32_t*>(&Ah[stage][r0 + 8][kb + 2 * q + 8]);
            }
            #pragma unroll
            for (int nt = 0; nt < 4; nt++) {
                int c0 = wn * 32 + nt * 8 + g;
                bf[nt][0] = *reinterpret_cast<const uint32_t*>(&Bh[stage][c0][kb + 2 * q]);
                bf[nt][1] = *reinterpret_cast<const uint32_t*>(&Bh[stage][c0][kb + 2 * q + 8]);
            }
            #pragma unroll
            for (int mt = 0; mt < 4; mt++)
                #pragma unroll
                for (int nt = 0; nt < 4; nt++)
                    mma_f16(c[mt][nt], af[mt], bf[nt]);
        }

        asm volatile("cp.async.wait_group 0;");
        __syncthreads();
        stage ^= 1;
    }

    #pragma unroll
    for (int mt = 0; mt < 4; mt++) {
        int row0 = bm + wm * 64 + mt * 16 + g;
        #pragma unroll
        for (int nt = 0; nt < 4; nt++) {
            int col = bn + wn * 32 + nt * 8 + 2 * q;
            if (row0 < M) {
                __half2 h01 = __floats2half2_rn(c[mt][nt][0], c[mt][nt][1]);
                *reinterpret_cast<__half2*>(C + (size_t)row0 * N + col) = h01;
            }
            if (row0 + 8 < M) {
                __half2 h23 = __floats2half2_rn(c[mt][nt][2], c[mt][nt][3]);
                *reinterpret_cast<__half2*>(C + (size_t)(row0 + 8) * N + col) = h23;
            }
        }
    }
}

// ---------------- CSR SpMM: warp per dst node, fp16 gather, fp32 accumulate ----------------
// Lane owns features [8*lane, 8*lane+8). One LDG.128 per row gather.
__device__ __forceinline__ void acc8(float* a, uint4 u, float w) {
    __half2* hp = reinterpret_cast<__half2*>(&u);
    #pragma unroll
    for (int t = 0; t < 4; t++) {
        float2 f = __half22float2(hp[t]);
        a[2 * t + 0] = fmaf(w, f.x, a[2 * t + 0]);
        a[2 * t + 1] = fmaf(w, f.y, a[2 * t + 1]);
    }
}

// HALF_OUT: relu(v + bias) -> fp16 (layer 1). else: raw fp32 (layer 2 -> d_out).
template<bool HALF_OUT>
__global__ __launch_bounds__(256) void k_spmm(
    const __half* __restrict__ h, void* __restrict__ out,
    const float* __restrict__ bias) {
    int node = blockIdx.x * 8 + (threadIdx.x >> 5);
    if (node >= N_NODES) return;
    int lane = threadIdx.x & 31;

    const uint4* hrow = reinterpret_cast<const uint4*>(h + (size_t)node * F_HID);
    float dd = g_dinv[node]; dd = dd * dd;

    float a[8] = {};
    acc8(a, hrow[lane], dd);

    int k   = g_offs[node];
    int end = k + g_cnt[node];
    for (; k + 1 < end; k += 2) {
        int2 p0 = g_csr[k], p1 = g_csr[k + 1];
        uint4 u0 = reinterpret_cast<const uint4*>(h + (size_t)p0.x * F_HID)[lane];
        uint4 u1 = reinterpret_cast<const uint4*>(h + (size_t)p1.x * F_HID)[lane];
        acc8(a, u0, __int_as_float(p0.y));
        acc8(a, u1, __int_as_float(p1.y));
    }
    if (k < end) {
        int2 p = g_csr[k];
        uint4 u = reinterpret_cast<const uint4*>(h + (size_t)p.x * F_HID)[lane];
        acc8(a, u, __int_as_float(p.y));
    }

    if (HALF_OUT) {
        const float4* b4 = reinterpret_cast<const float4*>(bias) + 2 * lane;
        float4 bb0 = b4[0], bb1 = b4[1];
        a[0] = fmaxf(a[0] + bb0.x, 0.f); a[1] = fmaxf(a[1] + bb0.y, 0.f);
        a[2] = fmaxf(a[2] + bb0.z, 0.f); a[3] = fmaxf(a[3] + bb0.w, 0.f);
        a[4] = fmaxf(a[4] + bb1.x, 0.f); a[5] = fmaxf(a[5] + bb1.y, 0.f);
        a[6] = fmaxf(a[6] + bb1.z, 0.f); a[7] = fmaxf(a[7] + bb1.w, 0.f);
        __half2 h0 = __floats2half2_rn(a[0], a[1]);
        __half2 h1 = __floats2half2_rn(a[2], a[3]);
        __half2 h2 = __floats2half2_rn(a[4], a[5]);
        __half2 h3 = __floats2half2_rn(a[6], a[7]);
        uint4 u;
        u.x = *reinterpret_cast<uint32_t*>(&h0);
        u.y = *reinterpret_cast<uint32_t*>(&h1);
        u.z = *reinterpret_cast<uint32_t*>(&h2);
        u.w = *reinterpret_cast<uint32_t*>(&h3);
        reinterpret_cast<uint4*>((__half*)out + (size_t)node * F_HID)[lane] = u;
    } else {
        float* op = (float*)out + (size_t)node * F_HID + 8 * lane;
        *reinterpret_cast<float4*>(op)     = make_float4(a[0], a[1], a[2], a[3]);
        *reinterpret_cast<float4*>(op + 4) = make_float4(a[4], a[5], a[6], a[7]);
    }
}

// ---------------- BatchNorm stats (over nodes), bias+relu fused ----------------
__global__ void k_bn_stats(const float* __restrict__ out, const float* __restrict__ b2) {
    int f = threadIdx.x;
    int row0 = blockIdx.x * 64;
    float bias = b2[f];
    float s = 0.f, s2 = 0.f;
    for (int r = 0; r < 64; r++) {
        int row = row0 + r;
        if (row >= N_NODES) break;
        float v = fmaxf(out[(size_t)row * F_OUT + f] + bias, 0.f);
        s += v; s2 += v * v;
    }
    atomicAdd(&g_colsum[f], s);
    atomicAdd(&g_colsumsq[f], s2);
}

// ---------------- final: bias+relu -> BN -> LN, in place; warp per row ----------------
__global__ __launch_bounds__(256) void k_bn_ln(
    float* __restrict__ out, const float* __restrict__ b2,
    const float* __restrict__ bng, const float* __restrict__ bnb,
    const float* __restrict__ lng, const float* __restrict__ lnb) {
    int row  = (int)((blockIdx.x * 256u + threadIdx.x) >> 5);
    int lane = threadIdx.x & 31;
    if (row >= N_NODES) return;
    float* rowp = out + (size_t)row * F_OUT;
    const float invN = 1.0f / (float)N_NODES;
    float y[8];
    float s = 0.f, s2 = 0.f;
    #pragma unroll
    for (int j = 0; j < 8; j++) {
        int f = lane + 32 * j;
        float v   = fmaxf(rowp[f] + b2[f], 0.f);
        float mu  = g_colsum[f] * invN;
        float var = g_colsumsq[f] * invN - mu * mu;
        float yy  = (v - mu) * rsqrtf(var + EPS) * bng[f] + bnb[f];
        y[j] = yy;
        s += yy; s2 += yy * yy;
    }
    #pragma unroll
    for (int o = 16; o; o >>= 1) {
        s  += __shfl_xor_sync(0xffffffffu, s, o);
        s2 += __shfl_xor_sync(0xffffffffu, s2, o);
    }
    float m   = s * (1.0f / F_OUT);
    float var = s2 * (1.0f / F_OUT) - m * m;
    float r   = rsqrtf(var + EPS);
    #pragma unroll
    for (int j = 0; j < 8; j++) {
        int f = lane + 32 * j;
        rowp[f] = (y[j] - m) * r * lng[f] + lnb[f];
    }
}

// ---------------- launch (round-5 proven prep order) ----------------
extern "C" void kernel_launch(void* const* d_in, const int* in_sizes, int n_in,
                              void* d_out, int out_size) {
    const float* x   = (const float*)d_in[0];
    const int*   ei  = (const int*)d_in[1];     // int32 (JAX x64 disabled)
    const float* ew  = (const float*)d_in[2];
    const float* W1  = (const float*)d_in[3];
    const float* b1  = (const float*)d_in[4];
    const float* W2  = (const float*)d_in[5];
    const float* b2  = (const float*)d_in[6];
    const float* bng = (const float*)d_in[7];
    const float* bnb = (const float*)d_in[8];
    const float* lng = (const float*)d_in[9];
    const float* lnb = (const float*)d_in[10];
    float* out = (float*)d_out;
    const int E = in_sizes[2];

    __half *hh, *xh, *aggh, *wh1, *wh2;
    cudaGetSymbolAddress((void**)&hh,   g_hh);
    cudaGetSymbolAddress((void**)&xh,   g_xh);
    cudaGetSymbolAddress((void**)&aggh, g_aggh);
    cudaGetSymbolAddress((void**)&wh1,  g_wh1);
    cudaGetSymbolAddress((void**)&wh2,  g_wh2);

    const int T = 256;
    // graph prep (round-5 order)
    k_init<<<(N_NODES + T - 1) / T, T>>>();
    k_deg_hist<<<(E + T - 1) / T, T>>>(ei, ew, E);
    k_dinv<<<(N_NODES + T - 1) / T, T>>>();
    k_scan1<<<NB_SCAN, 256>>>();
    k_scan2<<<1, 256>>>();
    k_scan3<<<(N_NODES + T - 1) / T, T>>>();
    k_fill<<<(E + T - 1) / T, T>>>(ei, ew, E);

    // fp16 conversions
    k_xhalf<<<(N_NODES * F_IN / 8 + T - 1) / T, T>>>(x, xh, N_NODES * F_IN / 8);
    k_wh<<<(F_IN * F_HID + T - 1) / T, T>>>(W1, wh1, F_IN, F_HID);
    k_wh<<<(F_HID * F_OUT + T - 1) / T, T>>>(W2, wh2, F_HID, F_OUT);

    // layer 1: h1 = x @ W1 (fp16 in/out, fp32 accum)
    {
        dim3 grid(F_HID / 128, (N_NODES + 127) / 128);
        k_hgemm<<<grid, 256>>>(xh, wh1, hh, N_NODES, F_IN, F_HID);
    }
    // agg1 = fp16(relu(D^-1/2 (A+I) D^-1/2 h1 + b1))
    k_spmm<true><<<N_NODES / 8, 256>>>(hh, aggh, b1);

    // layer 2: h2 = agg1 @ W2
    {
        dim3 grid(F_OUT / 128, (N_NODES + 127) / 128);
        k_hgemm<<<grid, 256>>>(aggh, wh2, hh, N_NODES, F_HID, F_OUT);
    }
    // agg2 (fp32) into d_out
    k_spmm<false><<<N_NODES / 8, 256>>>(hh, out, nullptr);

    // bias+relu fused into BN stats and finalize
    k_bn_stats<<<(N_NODES + 63) / 64, 256>>>(out, b2);
    k_bn_ln<<<(N_NODES + 7) / 8, 256>>>(out, b2, bng, bnb, lng, lnb);
}